// round 12
// baseline (speedup 1.0000x reference)
#include <cuda_runtime.h>
#include <cuda_bf16.h>
#include <cuda_fp16.h>
#include <math.h>
#include <stdint.h>

#define SQ   2048
#define NH   16
#define DD   1024
#define BB   2
#define MTOK 4096

// Scratch
__device__ float g_qkv[(size_t)MTOK * 3072];
__device__ half g_xh[(size_t)MTOK * DD];
__device__ half g_xl[(size_t)MTOK * DD];
__device__ half g_ah[(size_t)MTOK * DD];
__device__ half g_al[(size_t)MTOK * DD];
__device__ half g_wqh[(size_t)3072 * DD];   // W_qkv^T fp16
__device__ half g_woh[(size_t)DD * DD];     // W_out^T fp16

// ---------------- helpers ----------------
__device__ __forceinline__ uint32_t smem_u32(const void* p) {
    uint32_t a;
    asm("{ .reg .u64 t; cvta.to.shared.u64 t, %1; cvt.u32.u64 %0, t; }" : "=r"(a) : "l"(p));
    return a;
}
__device__ __forceinline__ void cpasync16(uint32_t dst, const void* src) {
    asm volatile("cp.async.cg.shared.global [%0], [%1], 16;\n" :: "r"(dst), "l"(src));
}
#define CP_COMMIT() asm volatile("cp.async.commit_group;\n" ::: "memory")
#define SWZ128(o) ((o) ^ (((o) >> 3) & 0x70))

__device__ __forceinline__ void ldsm4(uint32_t* r, uint32_t addr) {
    asm volatile("ldmatrix.sync.aligned.m8n8.x4.shared.b16 {%0,%1,%2,%3}, [%4];"
        : "=r"(r[0]), "=r"(r[1]), "=r"(r[2]), "=r"(r[3]) : "r"(addr));
}
__device__ __forceinline__ void mma_f16(float* c, const uint32_t* a, const uint32_t* b) {
    asm volatile(
        "mma.sync.aligned.m16n8k16.row.col.f32.f16.f16.f32 "
        "{%0,%1,%2,%3}, {%4,%5,%6,%7}, {%8,%9}, {%0,%1,%2,%3};"
        : "+f"(c[0]), "+f"(c[1]), "+f"(c[2]), "+f"(c[3])
        : "r"(a[0]), "r"(a[1]), "r"(a[2]), "r"(a[3]), "r"(b[0]), "r"(b[1]));
}

// ---------------- split kernels (fp16) ----------------
__global__ __launch_bounds__(256) void split_f16_kernel(
    const float4* __restrict__ in,
    half2* __restrict__ hi, half2* __restrict__ lo, int n4)
{
    int i = blockIdx.x * blockDim.x + threadIdx.x;
    if (i >= n4) return;
    float4 v = in[i];
    half hx = __float2half(v.x);
    half hy = __float2half(v.y);
    half hz = __float2half(v.z);
    half hw = __float2half(v.w);
    hi[2*i+0] = __halves2half2(hx, hy);
    hi[2*i+1] = __halves2half2(hz, hw);
    lo[2*i+0] = __floats2half2_rn(v.x - __half2float(hx), v.y - __half2float(hy));
    lo[2*i+1] = __floats2half2_rn(v.z - __half2float(hz), v.w - __half2float(hw));
}

// transpose + round: W fp32 [K][N] -> Wt fp16 [N][K]
__global__ __launch_bounds__(256) void tsplit_f16_kernel(
    const float* __restrict__ B, half* __restrict__ Bht, int K, int N)
{
    __shared__ float t[32][33];
    int n0 = blockIdx.x * 32, k0 = blockIdx.y * 32;
    for (int j = threadIdx.y; j < 32; j += 8)
        t[j][threadIdx.x] = B[(size_t)(k0 + j) * N + n0 + threadIdx.x];
    __syncthreads();
    for (int j = threadIdx.y; j < 32; j += 8)
        Bht[(size_t)(n0 + j) * K + k0 + threadIdx.x] = __float2half(t[threadIdx.x][j]);
}

// ============================================================
// fp16x2 GEMM: C = Ah*Bh + Al*Bh (A exact as fp16 pair, B rounded).
// Tile 256(M)x128(N), BK=64, 512 thr, 4x4 warps (64x32 tiles),
// 2-stage cp.async, SW128 smem, product-outermost MMA order.
// ============================================================
#define GT_AH  0
#define GT_AL  32768
#define GT_BH  65536
#define GSTGB  81920
#define GEMM_SMEM (2 * GSTGB + 1024)

__global__ __launch_bounds__(512) void gemm_f16x2(
    const half* __restrict__ Ah, const half* __restrict__ Al,
    const half* __restrict__ Bh,
    float* __restrict__ C, int M, int N, int K)
{
    extern __shared__ char gsm[];
    const uint32_t sbase = (smem_u32(gsm) + 1023u) & ~1023u;

    const int tid  = threadIdx.x;
    const int lane = tid & 31, wid = tid >> 5;
    const int wm   = wid >> 2, wn = wid & 3;
    const int g    = lane >> 2, t = lane & 3;
    const int row0 = blockIdx.y * 256;
    const int col0 = blockIdx.x * 128;
    const int nch  = K >> 6;

    const int aRow = lane & 15;
    const int aK   = (lane & 16) ? 8 : 0;
    const int bRow = (lane & 7) + ((lane & 16) ? 8 : 0);
    const int bK   = lane & 8;

    float acc[4][4][4];
    #pragma unroll
    for (int mt = 0; mt < 4; mt++)
        #pragma unroll
        for (int nt = 0; nt < 4; nt++)
            #pragma unroll
            for (int e = 0; e < 4; e++) acc[mt][nt][e] = 0.0f;

    auto load_chunk = [&](int c, int s) {
        const uint32_t base = sbase + (uint32_t)s * GSTGB;
        const int kk = c * 64;
        #pragma unroll
        for (int i = 0; i < 4; i++) {
            int u = tid + i * 512;              // 0..2047 (A: 256 rows x 8 x16B)
            int r = u >> 3, sg = u & 7;
            uint32_t so = SWZ128((uint32_t)(r * 128 + sg * 16));
            size_t go = (size_t)(row0 + r) * K + kk + sg * 8;
            cpasync16(base + GT_AH + so, Ah + go);
            cpasync16(base + GT_AL + so, Al + go);
        }
        #pragma unroll
        for (int i = 0; i < 2; i++) {
            int u = tid + i * 512;              // 0..1023 (B: 128 rows)
            int r = u >> 3, sg = u & 7;
            uint32_t so = SWZ128((uint32_t)(r * 128 + sg * 16));
            size_t go = (size_t)(col0 + r) * K + kk + sg * 8;
            cpasync16(base + GT_BH + so, Bh + go);
        }
    };

    load_chunk(0, 0); CP_COMMIT();

    for (int c = 0; c < nch; c++) {
        const int buf = c & 1;
        if (c + 1 < nch) { load_chunk(c + 1, buf ^ 1); CP_COMMIT(); }
        if (c + 1 < nch) asm volatile("cp.async.wait_group 1;\n" ::: "memory");
        else             asm volatile("cp.async.wait_group 0;\n" ::: "memory");
        __syncthreads();

        const uint32_t bAH = sbase + (uint32_t)buf * GSTGB + GT_AH;
        const uint32_t bAL = bAH + (GT_AL - GT_AH);
        const uint32_t bBH = bAH + (GT_BH - GT_AH);

        #pragma unroll
        for (int ks = 0; ks < 4; ks++) {
            const int kb = ks * 16;
            uint32_t afh[4][4], afl[4][4], bfh[2][4];
            #pragma unroll
            for (int mt = 0; mt < 4; mt++) {
                uint32_t so = SWZ128((uint32_t)((wm*64 + mt*16 + aRow) * 128 + (kb + aK) * 2));
                ldsm4(afh[mt], bAH + so);
                ldsm4(afl[mt], bAL + so);
            }
            #pragma unroll
            for (int p = 0; p < 2; p++) {
                uint32_t so = SWZ128((uint32_t)((wn*32 + p*16 + bRow) * 128 + (kb + bK) * 2));
                ldsm4(bfh[p], bBH + so);
            }
            // product-outermost: 16 distinct accs between revisits
            #pragma unroll
            for (int p = 0; p < 2; p++) {
                #pragma unroll
                for (int mt = 0; mt < 4; mt++) {
                    const uint32_t* a = p ? afl[mt] : afh[mt];
                    #pragma unroll
                    for (int nt = 0; nt < 4; nt++)
                        mma_f16(acc[mt][nt], a, &bfh[nt >> 1][(nt & 1) * 2]);
                }
            }
        }
        __syncthreads();
    }

    #pragma unroll
    for (int mt = 0; mt < 4; mt++) {
        #pragma unroll
        for (int nt = 0; nt < 4; nt++) {
            int r  = row0 + wm * 64 + mt * 16 + g;
            int cc = col0 + wn * 32 + nt * 8 + 2 * t;
            *(float2*)&C[(size_t)r * N + cc]       = make_float2(acc[mt][nt][0], acc[mt][nt][1]);
            *(float2*)&C[(size_t)(r + 8) * N + cc] = make_float2(acc[mt][nt][2], acc[mt][nt][3]);
        }
    }
}

// ============================================================
// Banded attention, 512 threads, fp16 split mma + bias prefetch.
// Epilogue now writes fp16 hi/lo pairs for the fp16x2 GEMM2.
// ============================================================
#define QP   72
#define VP   200
#define PSP  196
#define OF_QH  0
#define OF_QL  9216
#define OF_KH  18432
#define OF_KL  46080
#define OF_VH  73728
#define OF_VL  99328
#define OF_PS  124928
#define OF_PH  0
#define OF_PL  25600
#define ATTN_SMEM (124928 + 64*PSP*4)

__global__ __launch_bounds__(512) void attn_kernel(const float* __restrict__ traj)
{
    extern __shared__ char asmem[];
    half*  Qh = (half*)(asmem + OF_QH);
    half*  Ql = (half*)(asmem + OF_QL);
    half*  Kh = (half*)(asmem + OF_KH);
    half*  Kl = (half*)(asmem + OF_KL);
    half*  Vh = (half*)(asmem + OF_VH);
    half*  Vl = (half*)(asmem + OF_VL);
    float* Ps = (float*)(asmem + OF_PS);
    half*  Ph = (half*)(asmem + OF_PH);
    half*  Pl = (half*)(asmem + OF_PL);

    const int tid  = threadIdx.x;
    const int lane = tid & 31, wid = tid >> 5;
    const int wm   = wid >> 2, wn = wid & 3;
    const int g    = lane >> 2, t = lane & 3;
    const int b = blockIdx.z, h = blockIdx.y;
    const int q0 = blockIdx.x * 64;
    const int k0 = q0 - 128;
    const float NEGINF = __int_as_float(0xff800000);

    const int aRow = lane & 15;
    const int aK   = (lane & 16) ? 8 : 0;
    const int bRow = (lane & 7) + ((lane & 16) ? 8 : 0);
    const int bK   = lane & 8;

    const float* qkbase = g_qkv + (size_t)b * SQ * 3072;
    const float* bias = traj + (size_t)(b * NH + h) * SQ * SQ;

    // ---- prefetch bias band into Ps ----
    {
        const uint32_t psb = smem_u32(Ps);
        #pragma unroll
        for (int i = 0; i < 6; i++) {
            int u = tid + i * 512;
            int row = u / 48;
            int c4  = u % 48;
            int kg  = k0 + c4 * 4;
            if (kg >= 0) {
                cpasync16(psb + (uint32_t)(row * PSP + c4 * 4) * 4,
                          bias + (size_t)(q0 + row) * SQ + kg);
            }
        }
        CP_COMMIT();
    }

    // ---- load Q/K/V with hi/lo split ----
    for (int idx = tid; idx < 64 * 64; idx += 512) {
        int r = idx >> 6, d = idx & 63;
        float v = qkbase[(size_t)(q0 + r) * 3072 + h * 64 + d];
        half hh = __float2half(v);
        Qh[r * QP + d] = hh;
        Ql[r * QP + d] = __float2half(v - __half2float(hh));
    }
    for (int idx = tid; idx < 192 * 64; idx += 512) {
        int kk = idx >> 6, d = idx & 63;
        int key = k0 + kk;
        float kv = 0.0f, vv = 0.0f;
        if (key >= 0) {
            const float* p = qkbase + (size_t)key * 3072 + 1024 + h * 64 + d;
            kv = p[0];
            vv = p[1024];
        }
        half kh = __float2half(kv);
        Kh[kk * QP + d] = kh;
        Kl[kk * QP + d] = __float2half(kv - __half2float(kh));
        half vh = __float2half(vv);
        Vh[d * VP + kk] = vh;
        Vl[d * VP + kk] = __float2half(vv - __half2float(vh));
    }
    __syncthreads();

    // ---- scores: 3-pass fp16 mma, warp tile 16x48 ----
    float acc[6][4];
    #pragma unroll
    for (int nt = 0; nt < 6; nt++)
        #pragma unroll
        for (int e = 0; e < 4; e++) acc[nt][e] = 0.0f;

    #pragma unroll
    for (int seg = 0; seg < 3; seg++) {
        uint32_t aq = smem_u32(seg == 2 ? Ql : Qh);
        uint32_t bk = smem_u32(seg == 1 ? Kl : Kh);
        #pragma unroll
        for (int ks = 0; ks < 4; ks++) {
            const int kb = ks * 16;
            uint32_t af[4], bfr[3][4];
            ldsm4(af, aq + 2u * ((wm * 16 + aRow) * QP + kb + aK));
            #pragma unroll
            for (int p = 0; p < 3; p++)
                ldsm4(bfr[p], bk + 2u * ((wn * 48 + p * 16 + bRow) * QP + kb + bK));
            #pragma unroll
            for (int nt = 0; nt < 6; nt++)
                mma_f16(acc[nt], af, &bfr[nt >> 1][(nt & 1) * 2]);
        }
    }

    asm volatile("cp.async.wait_group 0;\n" ::: "memory");
    __syncthreads();

    // ---- scale + bias(smem) + mask -> Ps ----
    {
        #pragma unroll
        for (int nt = 0; nt < 6; nt++) {
            int rl = wm * 16 + g;
            int cl = wn * 48 + nt * 8 + 2 * t;
            #pragma unroll
            for (int e = 0; e < 4; e++) {
                int row = rl + ((e & 2) ? 8 : 0);
                int col = cl + (e & 1);
                int kg = k0 + col;
                float s;
                if (kg >= 0 && col >= row && col <= row + 128)
                    s = acc[nt][e] * 0.125f + Ps[row * PSP + col];
                else
                    s = NEGINF;
                Ps[row * PSP + col] = s;
            }
        }
    }
    __syncthreads();

    // ---- softmax (8 threads/row), write Ph/Pl ----
    {
        int row = tid >> 3, sub = tid & 7;
        float* prow = Ps + row * PSP + sub * 24;
        float m = NEGINF;
        #pragma unroll 8
        for (int i = 0; i < 24; i++) m = fmaxf(m, prow[i]);
        m = fmaxf(m, __shfl_xor_sync(0xffffffffu, m, 1));
        m = fmaxf(m, __shfl_xor_sync(0xffffffffu, m, 2));
        m = fmaxf(m, __shfl_xor_sync(0xffffffffu, m, 4));
        float ssum = 0.0f;
        float ebuf[24];
        #pragma unroll 8
        for (int i = 0; i < 24; i++) {
            float e = expf(prow[i] - m);
            ebuf[i] = e;
            ssum += e;
        }
        ssum += __shfl_xor_sync(0xffffffffu, ssum, 1);
        ssum += __shfl_xor_sync(0xffffffffu, ssum, 2);
        ssum += __shfl_xor_sync(0xffffffffu, ssum, 4);
        float inv = 1.0f / ssum;
        half* phrow = Ph + row * VP + sub * 24;
        half* plrow = Pl + row * VP + sub * 24;
        #pragma unroll 8
        for (int i = 0; i < 24; i++) {
            float pv = ebuf[i] * inv;
            half hh = __float2half(pv);
            phrow[i] = hh;
            plrow[i] = __float2half(pv - __half2float(hh));
        }
    }
    __syncthreads();

    // ---- O = PV: 3-pass fp16 mma, warp tile 16x16, k=192 ----
    float o[2][4];
    #pragma unroll
    for (int nt = 0; nt < 2; nt++)
        #pragma unroll
        for (int e = 0; e < 4; e++) o[nt][e] = 0.0f;

    #pragma unroll
    for (int seg = 0; seg < 3; seg++) {
        uint32_t ap = smem_u32(seg == 2 ? Pl : Ph);
        uint32_t bv = smem_u32(seg == 1 ? Vl : Vh);
        for (int ks = 0; ks < 12; ks++) {
            const int kb = ks * 16;
            uint32_t af[4], bfr[4];
            ldsm4(af, ap + 2u * ((wm * 16 + aRow) * VP + kb + aK));
            ldsm4(bfr, bv + 2u * ((wn * 16 + bRow) * VP + kb + bK));
            #pragma unroll
            for (int nt = 0; nt < 2; nt++)
                mma_f16(o[nt], af, &bfr[nt * 2]);
        }
    }

    // ---- epilogue: write fp16 hi/lo ----
    #pragma unroll
    for (int nt = 0; nt < 2; nt++) {
        int rl = wm * 16 + g;
        int d  = wn * 16 + nt * 8 + 2 * t;
        #pragma unroll
        for (int half_i = 0; half_i < 2; half_i++) {
            int row = rl + half_i * 8;
            float v0 = o[nt][half_i * 2 + 0];
            float v1 = o[nt][half_i * 2 + 1];
            half h0 = __float2half(v0);
            half h1 = __float2half(v1);
            size_t off = (size_t)(b * SQ + q0 + row) * DD + h * 64 + d;
            *(half2*)(g_ah + off) = __halves2half2(h0, h1);
            *(half2*)(g_al + off) = __floats2half2_rn(
                v0 - __half2float(h0), v1 - __half2float(h1));
        }
    }
}

// ============================================================
// Launch
// ============================================================
extern "C" void kernel_launch(void* const* d_in, const int* in_sizes, int n_in,
                              void* d_out, int out_size)
{
    const float* x    = (const float*)d_in[0];
    const float* traj = (const float*)d_in[1];
    const float* Wqkv = (const float*)d_in[3];
    const float* Wout = (const float*)d_in[4];
    float* out = (float*)d_out;

    void* p;
    cudaGetSymbolAddress(&p, g_qkv);  float* qkv = (float*)p;
    cudaGetSymbolAddress(&p, g_xh);   half* xh = (half*)p;
    cudaGetSymbolAddress(&p, g_xl);   half* xl = (half*)p;
    cudaGetSymbolAddress(&p, g_ah);   half* ah = (half*)p;
    cudaGetSymbolAddress(&p, g_al);   half* al = (half*)p;
    cudaGetSymbolAddress(&p, g_wqh);  half* wqh = (half*)p;
    cudaGetSymbolAddress(&p, g_woh);  half* woh = (half*)p;

    // split x into fp16 hi/lo
    {
        int n4 = MTOK * DD / 4;
        split_f16_kernel<<<(n4 + 255) / 256, 256>>>(
            (const float4*)x, (half2*)xh, (half2*)xl, n4);
    }
    // transpose + round weights to fp16
    {
        dim3 grid(3072 / 32, DD / 32);
        tsplit_f16_kernel<<<grid, dim3(32, 8)>>>(Wqkv, wqh, DD, 3072);
    }
    {
        dim3 grid(DD / 32, DD / 32);
        tsplit_f16_kernel<<<grid, dim3(32, 8)>>>(Wout, woh, DD, DD);
    }
    // GEMM1: qkv = x @ W_qkv (fp16x2)
    {
        cudaFuncSetAttribute(gemm_f16x2,
            cudaFuncAttributeMaxDynamicSharedMemorySize, GEMM_SMEM);
        dim3 grid(3072 / 128, MTOK / 256);
        gemm_f16x2<<<grid, 512, GEMM_SMEM>>>(xh, xl, wqh, qkv, MTOK, 3072, DD);
    }
    // attention
    {
        cudaFuncSetAttribute(attn_kernel,
            cudaFuncAttributeMaxDynamicSharedMemorySize, ATTN_SMEM);
        dim3 grid(SQ / 64, NH, BB);
        attn_kernel<<<grid, 512, ATTN_SMEM>>>(traj);
    }
    // GEMM2: out = att @ W_out (fp16x2)
    {
        dim3 grid(DD / 128, MTOK / 256);
        gemm_f16x2<<<grid, 512, GEMM_SMEM>>>(ah, al, woh, out, MTOK, DD, DD);
    }
}

// round 14
// speedup vs baseline: 1.2053x; 1.2053x over previous
#include <cuda_runtime.h>
#include <cuda_bf16.h>
#include <cuda_fp16.h>
#include <math.h>
#include <stdint.h>

#define SQ   2048
#define NH   16
#define DD   1024
#define BB   2
#define MTOK 4096

// Scratch
__device__ float g_qkv[(size_t)MTOK * 3072];
__device__ __nv_bfloat16 g_xh[(size_t)MTOK * DD];
__device__ __nv_bfloat16 g_xl[(size_t)MTOK * DD];
__device__ __nv_bfloat16 g_ah[(size_t)MTOK * DD];
__device__ __nv_bfloat16 g_al[(size_t)MTOK * DD];
__device__ __nv_bfloat16 g_wqh[(size_t)3072 * DD];
__device__ __nv_bfloat16 g_wql[(size_t)3072 * DD];
__device__ __nv_bfloat16 g_woh[(size_t)DD * DD];
__device__ __nv_bfloat16 g_wol[(size_t)DD * DD];

// ---------------- helpers ----------------
__device__ __forceinline__ uint32_t smem_u32(const void* p) {
    uint32_t a;
    asm("{ .reg .u64 t; cvta.to.shared.u64 t, %1; cvt.u32.u64 %0, t; }" : "=r"(a) : "l"(p));
    return a;
}
__device__ __forceinline__ void cpasync16(uint32_t dst, const void* src) {
    asm volatile("cp.async.cg.shared.global [%0], [%1], 16;\n" :: "r"(dst), "l"(src));
}
#define CP_COMMIT() asm volatile("cp.async.commit_group;\n" ::: "memory")
#define SWZ128(o) ((o) ^ (((o) >> 3) & 0x70))

__device__ __forceinline__ void ldsm4(uint32_t* r, uint32_t addr) {
    asm volatile("ldmatrix.sync.aligned.m8n8.x4.shared.b16 {%0,%1,%2,%3}, [%4];"
        : "=r"(r[0]), "=r"(r[1]), "=r"(r[2]), "=r"(r[3]) : "r"(addr));
}
__device__ __forceinline__ void mma_bf16(float* c, const uint32_t* a, const uint32_t* b) {
    asm volatile(
        "mma.sync.aligned.m16n8k16.row.col.f32.bf16.bf16.f32 "
        "{%0,%1,%2,%3}, {%4,%5,%6,%7}, {%8,%9}, {%0,%1,%2,%3};"
        : "+f"(c[0]), "+f"(c[1]), "+f"(c[2]), "+f"(c[3])
        : "r"(a[0]), "r"(a[1]), "r"(a[2]), "r"(a[3]), "r"(b[0]), "r"(b[1]));
}

// ---------------- split kernels ----------------
__global__ __launch_bounds__(256) void split_kernel(
    const float4* __restrict__ in,
    __nv_bfloat162* __restrict__ hi, __nv_bfloat162* __restrict__ lo, int n4)
{
    int i = blockIdx.x * blockDim.x + threadIdx.x;
    if (i >= n4) return;
    float4 v = in[i];
    __nv_bfloat16 hx = __float2bfloat16(v.x);
    __nv_bfloat16 hy = __float2bfloat16(v.y);
    __nv_bfloat16 hz = __float2bfloat16(v.z);
    __nv_bfloat16 hw = __float2bfloat16(v.w);
    hi[2*i+0] = __nv_bfloat162(hx, hy);
    hi[2*i+1] = __nv_bfloat162(hz, hw);
    lo[2*i+0] = __floats2bfloat162_rn(v.x - __bfloat162float(hx), v.y - __bfloat162float(hy));
    lo[2*i+1] = __floats2bfloat162_rn(v.z - __bfloat162float(hz), v.w - __bfloat162float(hw));
}

__global__ __launch_bounds__(256) void tsplit_kernel(
    const float* __restrict__ B,
    __nv_bfloat16* __restrict__ Bht, __nv_bfloat16* __restrict__ Blt,
    int K, int N)
{
    __shared__ float t[32][33];
    int n0 = blockIdx.x * 32, k0 = blockIdx.y * 32;
    for (int j = threadIdx.y; j < 32; j += 8)
        t[j][threadIdx.x] = B[(size_t)(k0 + j) * N + n0 + threadIdx.x];
    __syncthreads();
    for (int j = threadIdx.y; j < 32; j += 8) {
        float v = t[threadIdx.x][j];
        __nv_bfloat16 h = __float2bfloat16(v);
        size_t o = (size_t)(n0 + j) * K + k0 + threadIdx.x;
        Bht[o] = h;
        Blt[o] = __float2bfloat16(v - __bfloat162float(h));
    }
}

// ============================================================
// bf16x3 fused GEMM (R11 engine, proven). Tile 256x128, BK=64,
// 512 thr, 4x4 warps (64x32 tiles), 2-stage cp.async, SW128 smem,
// product-outermost MMA order.
// ============================================================
#define GT_AH  0
#define GT_AL  32768
#define GT_BH  65536
#define GT_BL  81920
#define GSTGB  98304
#define GEMM_SMEM (2 * GSTGB + 1024)

__global__ __launch_bounds__(512) void gemm_bf16x3(
    const __nv_bfloat16* __restrict__ Ah, const __nv_bfloat16* __restrict__ Al,
    const __nv_bfloat16* __restrict__ Bh, const __nv_bfloat16* __restrict__ Bl,
    float* __restrict__ C, int M, int N, int K)
{
    extern __shared__ char gsm[];
    const uint32_t sbase = (smem_u32(gsm) + 1023u) & ~1023u;

    const int tid  = threadIdx.x;
    const int lane = tid & 31, wid = tid >> 5;
    const int wm   = wid >> 2, wn = wid & 3;
    const int g    = lane >> 2, t = lane & 3;
    const int row0 = blockIdx.y * 256;
    const int col0 = blockIdx.x * 128;
    const int nch  = K >> 6;

    const int aRow = lane & 15;
    const int aK   = (lane & 16) ? 8 : 0;
    const int bRow = (lane & 7) + ((lane & 16) ? 8 : 0);
    const int bK   = lane & 8;

    float acc[4][4][4];
    #pragma unroll
    for (int mt = 0; mt < 4; mt++)
        #pragma unroll
        for (int nt = 0; nt < 4; nt++)
            #pragma unroll
            for (int e = 0; e < 4; e++) acc[mt][nt][e] = 0.0f;

    auto load_chunk = [&](int c, int s) {
        const uint32_t base = sbase + (uint32_t)s * GSTGB;
        const int kk = c * 64;
        #pragma unroll
        for (int i = 0; i < 4; i++) {
            int u = tid + i * 512;
            int r = u >> 3, sg = u & 7;
            uint32_t so = SWZ128((uint32_t)(r * 128 + sg * 16));
            size_t go = (size_t)(row0 + r) * K + kk + sg * 8;
            cpasync16(base + GT_AH + so, Ah + go);
            cpasync16(base + GT_AL + so, Al + go);
        }
        #pragma unroll
        for (int i = 0; i < 2; i++) {
            int u = tid + i * 512;
            int r = u >> 3, sg = u & 7;
            uint32_t so = SWZ128((uint32_t)(r * 128 + sg * 16));
            size_t go = (size_t)(col0 + r) * K + kk + sg * 8;
            cpasync16(base + GT_BH + so, Bh + go);
            cpasync16(base + GT_BL + so, Bl + go);
        }
    };

    load_chunk(0, 0); CP_COMMIT();

    for (int c = 0; c < nch; c++) {
        const int buf = c & 1;
        if (c + 1 < nch) { load_chunk(c + 1, buf ^ 1); CP_COMMIT(); }
        if (c + 1 < nch) asm volatile("cp.async.wait_group 1;\n" ::: "memory");
        else             asm volatile("cp.async.wait_group 0;\n" ::: "memory");
        __syncthreads();

        const uint32_t bAH = sbase + (uint32_t)buf * GSTGB + GT_AH;
        const uint32_t bAL = bAH + (GT_AL - GT_AH);
        const uint32_t bBH = bAH + (GT_BH - GT_AH);
        const uint32_t bBL = bAH + (GT_BL - GT_AH);

        #pragma unroll
        for (int ks = 0; ks < 4; ks++) {
            const int kb = ks * 16;
            uint32_t afh[4][4], afl[4][4], bfh[2][4], bfl[2][4];
            #pragma unroll
            for (int mt = 0; mt < 4; mt++) {
                uint32_t so = SWZ128((uint32_t)((wm*64 + mt*16 + aRow) * 128 + (kb + aK) * 2));
                ldsm4(afh[mt], bAH + so);
                ldsm4(afl[mt], bAL + so);
            }
            #pragma unroll
            for (int p = 0; p < 2; p++) {
                uint32_t so = SWZ128((uint32_t)((wn*32 + p*16 + bRow) * 128 + (kb + bK) * 2));
                ldsm4(bfh[p], bBH + so);
                ldsm4(bfl[p], bBL + so);
            }
            #pragma unroll
            for (int p = 0; p < 3; p++) {
                #pragma unroll
                for (int mt = 0; mt < 4; mt++) {
                    const uint32_t* a = (p < 2) ? afh[mt] : afl[mt];
                    #pragma unroll
                    for (int nt = 0; nt < 4; nt++) {
                        const uint32_t* b = (p == 1)
                            ? &bfl[nt >> 1][(nt & 1) * 2]
                            : &bfh[nt >> 1][(nt & 1) * 2];
                        mma_bf16(acc[mt][nt], a, b);
                    }
                }
            }
        }
        __syncthreads();
    }

    #pragma unroll
    for (int mt = 0; mt < 4; mt++) {
        #pragma unroll
        for (int nt = 0; nt < 4; nt++) {
            int r  = row0 + wm * 64 + mt * 16 + g;
            int cc = col0 + wn * 32 + nt * 8 + 2 * t;
            *(float2*)&C[(size_t)r * N + cc]       = make_float2(acc[mt][nt][0], acc[mt][nt][1]);
            *(float2*)&C[(size_t)(r + 8) * N + cc] = make_float2(acc[mt][nt][2], acc[mt][nt][3]);
        }
    }
}

// ============================================================
// Banded attention, 512 threads, bf16 split mma (fast HMMA path)
// + cp.async bias prefetch. Structure identical to R11.
// ============================================================
#define QP   72
#define VP   200
#define PSP  196
#define OF_QH  0
#define OF_QL  9216
#define OF_KH  18432
#define OF_KL  46080
#define OF_VH  73728
#define OF_VL  99328
#define OF_PS  124928
#define OF_PH  0
#define OF_PL  25600
#define ATTN_SMEM (124928 + 64*PSP*4)

__global__ __launch_bounds__(512) void attn_kernel(const float* __restrict__ traj)
{
    extern __shared__ char asmem[];
    __nv_bfloat16* Qh = (__nv_bfloat16*)(asmem + OF_QH);
    __nv_bfloat16* Ql = (__nv_bfloat16*)(asmem + OF_QL);
    __nv_bfloat16* Kh = (__nv_bfloat16*)(asmem + OF_KH);
    __nv_bfloat16* Kl = (__nv_bfloat16*)(asmem + OF_KL);
    __nv_bfloat16* Vh = (__nv_bfloat16*)(asmem + OF_VH);
    __nv_bfloat16* Vl = (__nv_bfloat16*)(asmem + OF_VL);
    float* Ps = (float*)(asmem + OF_PS);
    __nv_bfloat16* Ph = (__nv_bfloat16*)(asmem + OF_PH);
    __nv_bfloat16* Pl = (__nv_bfloat16*)(asmem + OF_PL);

    const int tid  = threadIdx.x;
    const int lane = tid & 31, wid = tid >> 5;
    const int wm   = wid >> 2, wn = wid & 3;
    const int g    = lane >> 2, t = lane & 3;
    const int b = blockIdx.z, h = blockIdx.y;
    const int q0 = blockIdx.x * 64;
    const int k0 = q0 - 128;
    const float NEGINF = __int_as_float(0xff800000);

    const int aRow = lane & 15;
    const int aK   = (lane & 16) ? 8 : 0;
    const int bRow = (lane & 7) + ((lane & 16) ? 8 : 0);
    const int bK   = lane & 8;

    const float* qkbase = g_qkv + (size_t)b * SQ * 3072;
    const float* bias = traj + (size_t)(b * NH + h) * SQ * SQ;

    // ---- prefetch bias band into Ps ----
    {
        const uint32_t psb = smem_u32(Ps);
        #pragma unroll
        for (int i = 0; i < 6; i++) {
            int u = tid + i * 512;
            int row = u / 48;
            int c4  = u % 48;
            int kg  = k0 + c4 * 4;
            if (kg >= 0) {
                cpasync16(psb + (uint32_t)(row * PSP + c4 * 4) * 4,
                          bias + (size_t)(q0 + row) * SQ + kg);
            }
        }
        CP_COMMIT();
    }

    // ---- load Q/K/V with bf16 hi/lo split ----
    for (int idx = tid; idx < 64 * 64; idx += 512) {
        int r = idx >> 6, d = idx & 63;
        float v = qkbase[(size_t)(q0 + r) * 3072 + h * 64 + d];
        __nv_bfloat16 hh = __float2bfloat16(v);
        Qh[r * QP + d] = hh;
        Ql[r * QP + d] = __float2bfloat16(v - __bfloat162float(hh));
    }
    for (int idx = tid; idx < 192 * 64; idx += 512) {
        int kk = idx >> 6, d = idx & 63;
        int key = k0 + kk;
        float kv = 0.0f, vv = 0.0f;
        if (key >= 0) {
            const float* p = qkbase + (size_t)key * 3072 + 1024 + h * 64 + d;
            kv = p[0];
            vv = p[1024];
        }
        __nv_bfloat16 kh = __float2bfloat16(kv);
        Kh[kk * QP + d] = kh;
        Kl[kk * QP + d] = __float2bfloat16(kv - __bfloat162float(kh));
        __nv_bfloat16 vh = __float2bfloat16(vv);
        Vh[d * VP + kk] = vh;
        Vl[d * VP + kk] = __float2bfloat16(vv - __bfloat162float(vh));
    }
    __syncthreads();

    // ---- scores: 3-pass bf16 mma, warp tile 16x48 ----
    float acc[6][4];
    #pragma unroll
    for (int nt = 0; nt < 6; nt++)
        #pragma unroll
        for (int e = 0; e < 4; e++) acc[nt][e] = 0.0f;

    #pragma unroll
    for (int seg = 0; seg < 3; seg++) {
        uint32_t aq = smem_u32(seg == 2 ? Ql : Qh);
        uint32_t bk = smem_u32(seg == 1 ? Kl : Kh);
        #pragma unroll
        for (int ks = 0; ks < 4; ks++) {
            const int kb = ks * 16;
            uint32_t af[4], bfr[3][4];
            ldsm4(af, aq + 2u * ((wm * 16 + aRow) * QP + kb + aK));
            #pragma unroll
            for (int p = 0; p < 3; p++)
                ldsm4(bfr[p], bk + 2u * ((wn * 48 + p * 16 + bRow) * QP + kb + bK));
            #pragma unroll
            for (int nt = 0; nt < 6; nt++)
                mma_bf16(acc[nt], af, &bfr[nt >> 1][(nt & 1) * 2]);
        }
    }

    asm volatile("cp.async.wait_group 0;\n" ::: "memory");
    __syncthreads();

    // ---- scale + bias(smem) + mask -> Ps ----
    {
        #pragma unroll
        for (int nt = 0; nt < 6; nt++) {
            int rl = wm * 16 + g;
            int cl = wn * 48 + nt * 8 + 2 * t;
            #pragma unroll
            for (int e = 0; e < 4; e++) {
                int row = rl + ((e & 2) ? 8 : 0);
                int col = cl + (e & 1);
                int kg = k0 + col;
                float s;
                if (kg >= 0 && col >= row && col <= row + 128)
                    s = acc[nt][e] * 0.125f + Ps[row * PSP + col];
                else
                    s = NEGINF;
                Ps[row * PSP + col] = s;
            }
        }
    }
    __syncthreads();

    // ---- softmax (8 threads/row), write Ph/Pl (bf16) ----
    {
        int row = tid >> 3, sub = tid & 7;
        float* prow = Ps + row * PSP + sub * 24;
        float m = NEGINF;
        #pragma unroll 8
        for (int i = 0; i < 24; i++) m = fmaxf(m, prow[i]);
        m = fmaxf(m, __shfl_xor_sync(0xffffffffu, m, 1));
        m = fmaxf(m, __shfl_xor_sync(0xffffffffu, m, 2));
        m = fmaxf(m, __shfl_xor_sync(0xffffffffu, m, 4));
        float ssum = 0.0f;
        float ebuf[24];
        #pragma unroll 8
        for (int i = 0; i < 24; i++) {
            float e = expf(prow[i] - m);
            ebuf[i] = e;
            ssum += e;
        }
        ssum += __shfl_xor_sync(0xffffffffu, ssum, 1);
        ssum += __shfl_xor_sync(0xffffffffu, ssum, 2);
        ssum += __shfl_xor_sync(0xffffffffu, ssum, 4);
        float inv = 1.0f / ssum;
        __nv_bfloat16* phrow = Ph + row * VP + sub * 24;
        __nv_bfloat16* plrow = Pl + row * VP + sub * 24;
        #pragma unroll 8
        for (int i = 0; i < 24; i++) {
            float pv = ebuf[i] * inv;
            __nv_bfloat16 hh = __float2bfloat16(pv);
            phrow[i] = hh;
            plrow[i] = __float2bfloat16(pv - __bfloat162float(hh));
        }
    }
    __syncthreads();

    // ---- O = PV: 3-pass bf16 mma, warp tile 16x16, k=192 ----
    float o[2][4];
    #pragma unroll
    for (int nt = 0; nt < 2; nt++)
        #pragma unroll
        for (int e = 0; e < 4; e++) o[nt][e] = 0.0f;

    #pragma unroll
    for (int seg = 0; seg < 3; seg++) {
        uint32_t ap = smem_u32(seg == 2 ? Pl : Ph);
        uint32_t bv = smem_u32(seg == 1 ? Vl : Vh);
        for (int ks = 0; ks < 12; ks++) {
            const int kb = ks * 16;
            uint32_t af[4], bfr[4];
            ldsm4(af, ap + 2u * ((wm * 16 + aRow) * VP + kb + aK));
            ldsm4(bfr, bv + 2u * ((wn * 16 + bRow) * VP + kb + bK));
            #pragma unroll
            for (int nt = 0; nt < 2; nt++)
                mma_bf16(o[nt], af, &bfr[nt * 2]);
        }
    }

    // ---- epilogue: write bf16 hi/lo ----
    #pragma unroll
    for (int nt = 0; nt < 2; nt++) {
        int rl = wm * 16 + g;
        int d  = wn * 16 + nt * 8 + 2 * t;
        #pragma unroll
        for (int half_i = 0; half_i < 2; half_i++) {
            int row = rl + half_i * 8;
            float v0 = o[nt][half_i * 2 + 0];
            float v1 = o[nt][half_i * 2 + 1];
            __nv_bfloat16 h0 = __float2bfloat16(v0);
            __nv_bfloat16 h1 = __float2bfloat16(v1);
            size_t off = (size_t)(b * SQ + q0 + row) * DD + h * 64 + d;
            *(__nv_bfloat162*)(g_ah + off) = __nv_bfloat162(h0, h1);
            *(__nv_bfloat162*)(g_al + off) = __floats2bfloat162_rn(
                v0 - __bfloat162float(h0), v1 - __bfloat162float(h1));
        }
    }
}

// ============================================================
// Launch
// ============================================================
extern "C" void kernel_launch(void* const* d_in, const int* in_sizes, int n_in,
                              void* d_out, int out_size)
{
    const float* x    = (const float*)d_in[0];
    const float* traj = (const float*)d_in[1];
    const float* Wqkv = (const float*)d_in[3];
    const float* Wout = (const float*)d_in[4];
    float* out = (float*)d_out;

    void* p;
    cudaGetSymbolAddress(&p, g_qkv);  float* qkv = (float*)p;
    cudaGetSymbolAddress(&p, g_xh);   __nv_bfloat16* xh = (__nv_bfloat16*)p;
    cudaGetSymbolAddress(&p, g_xl);   __nv_bfloat16* xl = (__nv_bfloat16*)p;
    cudaGetSymbolAddress(&p, g_ah);   __nv_bfloat16* ah = (__nv_bfloat16*)p;
    cudaGetSymbolAddress(&p, g_al);   __nv_bfloat16* al = (__nv_bfloat16*)p;
    cudaGetSymbolAddress(&p, g_wqh);  __nv_bfloat16* wqh = (__nv_bfloat16*)p;
    cudaGetSymbolAddress(&p, g_wql);  __nv_bfloat16* wql = (__nv_bfloat16*)p;
    cudaGetSymbolAddress(&p, g_woh);  __nv_bfloat16* woh = (__nv_bfloat16*)p;
    cudaGetSymbolAddress(&p, g_wol);  __nv_bfloat16* wol = (__nv_bfloat16*)p;

    // split x
    {
        int n4 = MTOK * DD / 4;
        split_kernel<<<(n4 + 255) / 256, 256>>>(
            (const float4*)x, (__nv_bfloat162*)xh, (__nv_bfloat162*)xl, n4);
    }
    // transpose+split weights
    {
        dim3 grid(3072 / 32, DD / 32);
        tsplit_kernel<<<grid, dim3(32, 8)>>>(Wqkv, wqh, wql, DD, 3072);
    }
    {
        dim3 grid(DD / 32, DD / 32);
        tsplit_kernel<<<grid, dim3(32, 8)>>>(Wout, woh, wol, DD, DD);
    }
    // GEMM1: qkv = x @ W_qkv
    {
        cudaFuncSetAttribute(gemm_bf16x3,
            cudaFuncAttributeMaxDynamicSharedMemorySize, GEMM_SMEM);
        dim3 grid(3072 / 128, MTOK / 256);
        gemm_bf16x3<<<grid, 512, GEMM_SMEM>>>(xh, xl, wqh, wql, qkv, MTOK, 3072, DD);
    }
    // attention
    {
        cudaFuncSetAttribute(attn_kernel,
            cudaFuncAttributeMaxDynamicSharedMemorySize, ATTN_SMEM);
        dim3 grid(SQ / 64, NH, BB);
        attn_kernel<<<grid, 512, ATTN_SMEM>>>(traj);
    }
    // GEMM2: out = att @ W_out
    {
        dim3 grid(DD / 128, MTOK / 256);
        gemm_bf16x3<<<grid, 512, GEMM_SMEM>>>(ah, al, woh, wol, out, MTOK, DD, DD);
    }
}

// round 16
// speedup vs baseline: 1.2326x; 1.0226x over previous
#include <cuda_runtime.h>
#include <cuda_bf16.h>
#include <cuda_fp16.h>
#include <math.h>
#include <stdint.h>

#define SQ   2048
#define NH   16
#define DD   1024
#define BB   2
#define MTOK 4096

// Scratch
__device__ float g_qkv[(size_t)MTOK * 3072];
__device__ __nv_bfloat16 g_xh[(size_t)MTOK * DD];
__device__ __nv_bfloat16 g_xl[(size_t)MTOK * DD];
__device__ __nv_bfloat16 g_ah[(size_t)MTOK * DD];
__device__ __nv_bfloat16 g_al[(size_t)MTOK * DD];
__device__ __nv_bfloat16 g_wqh[(size_t)3072 * DD];
__device__ __nv_bfloat16 g_wql[(size_t)3072 * DD];
__device__ __nv_bfloat16 g_woh[(size_t)DD * DD];
__device__ __nv_bfloat16 g_wol[(size_t)DD * DD];

// ---------------- helpers ----------------
__device__ __forceinline__ uint32_t smem_u32(const void* p) {
    uint32_t a;
    asm("{ .reg .u64 t; cvta.to.shared.u64 t, %1; cvt.u32.u64 %0, t; }" : "=r"(a) : "l"(p));
    return a;
}
__device__ __forceinline__ void cpasync16(uint32_t dst, const void* src) {
    asm volatile("cp.async.cg.shared.global [%0], [%1], 16;\n" :: "r"(dst), "l"(src));
}
#define CP_COMMIT() asm volatile("cp.async.commit_group;\n" ::: "memory")
#define SWZ128(o) ((o) ^ (((o) >> 3) & 0x70))

__device__ __forceinline__ void ldsm4(uint32_t* r, uint32_t addr) {
    asm volatile("ldmatrix.sync.aligned.m8n8.x4.shared.b16 {%0,%1,%2,%3}, [%4];"
        : "=r"(r[0]), "=r"(r[1]), "=r"(r[2]), "=r"(r[3]) : "r"(addr));
}
__device__ __forceinline__ void mma_bf16(float* c, const uint32_t* a, const uint32_t* b) {
    asm volatile(
        "mma.sync.aligned.m16n8k16.row.col.f32.bf16.bf16.f32 "
        "{%0,%1,%2,%3}, {%4,%5,%6,%7}, {%8,%9}, {%0,%1,%2,%3};"
        : "+f"(c[0]), "+f"(c[1]), "+f"(c[2]), "+f"(c[3])
        : "r"(a[0]), "r"(a[1]), "r"(a[2]), "r"(a[3]), "r"(b[0]), "r"(b[1]));
}

// ---------------- split kernels ----------------
__global__ __launch_bounds__(256) void split_kernel(
    const float4* __restrict__ in,
    __nv_bfloat162* __restrict__ hi, __nv_bfloat162* __restrict__ lo, int n4)
{
    int i = blockIdx.x * blockDim.x + threadIdx.x;
    if (i >= n4) return;
    float4 v = in[i];
    __nv_bfloat16 hx = __float2bfloat16(v.x);
    __nv_bfloat16 hy = __float2bfloat16(v.y);
    __nv_bfloat16 hz = __float2bfloat16(v.z);
    __nv_bfloat16 hw = __float2bfloat16(v.w);
    hi[2*i+0] = __nv_bfloat162(hx, hy);
    hi[2*i+1] = __nv_bfloat162(hz, hw);
    lo[2*i+0] = __floats2bfloat162_rn(v.x - __bfloat162float(hx), v.y - __bfloat162float(hy));
    lo[2*i+1] = __floats2bfloat162_rn(v.z - __bfloat162float(hz), v.w - __bfloat162float(hw));
}

__global__ __launch_bounds__(256) void tsplit_kernel(
    const float* __restrict__ B,
    __nv_bfloat16* __restrict__ Bht, __nv_bfloat16* __restrict__ Blt,
    int K, int N)
{
    __shared__ float t[32][33];
    int n0 = blockIdx.x * 32, k0 = blockIdx.y * 32;
    for (int j = threadIdx.y; j < 32; j += 8)
        t[j][threadIdx.x] = B[(size_t)(k0 + j) * N + n0 + threadIdx.x];
    __syncthreads();
    for (int j = threadIdx.y; j < 32; j += 8) {
        float v = t[threadIdx.x][j];
        __nv_bfloat16 h = __float2bfloat16(v);
        size_t o = (size_t)(n0 + j) * K + k0 + threadIdx.x;
        Bht[o] = h;
        Blt[o] = __float2bfloat16(v - __bfloat162float(h));
    }
}

// ============================================================
// bf16x3 fused GEMM (R11 engine, proven; untouched).
// ============================================================
#define GT_AH  0
#define GT_AL  32768
#define GT_BH  65536
#define GT_BL  81920
#define GSTGB  98304
#define GEMM_SMEM (2 * GSTGB + 1024)

__global__ __launch_bounds__(512) void gemm_bf16x3(
    const __nv_bfloat16* __restrict__ Ah, const __nv_bfloat16* __restrict__ Al,
    const __nv_bfloat16* __restrict__ Bh, const __nv_bfloat16* __restrict__ Bl,
    float* __restrict__ C, int M, int N, int K)
{
    extern __shared__ char gsm[];
    const uint32_t sbase = (smem_u32(gsm) + 1023u) & ~1023u;

    const int tid  = threadIdx.x;
    const int lane = tid & 31, wid = tid >> 5;
    const int wm   = wid >> 2, wn = wid & 3;
    const int g    = lane >> 2, t = lane & 3;
    const int row0 = blockIdx.y * 256;
    const int col0 = blockIdx.x * 128;
    const int nch  = K >> 6;

    const int aRow = lane & 15;
    const int aK   = (lane & 16) ? 8 : 0;
    const int bRow = (lane & 7) + ((lane & 16) ? 8 : 0);
    const int bK   = lane & 8;

    float acc[4][4][4];
    #pragma unroll
    for (int mt = 0; mt < 4; mt++)
        #pragma unroll
        for (int nt = 0; nt < 4; nt++)
            #pragma unroll
            for (int e = 0; e < 4; e++) acc[mt][nt][e] = 0.0f;

    auto load_chunk = [&](int c, int s) {
        const uint32_t base = sbase + (uint32_t)s * GSTGB;
        const int kk = c * 64;
        #pragma unroll
        for (int i = 0; i < 4; i++) {
            int u = tid + i * 512;
            int r = u >> 3, sg = u & 7;
            uint32_t so = SWZ128((uint32_t)(r * 128 + sg * 16));
            size_t go = (size_t)(row0 + r) * K + kk + sg * 8;
            cpasync16(base + GT_AH + so, Ah + go);
            cpasync16(base + GT_AL + so, Al + go);
        }
        #pragma unroll
        for (int i = 0; i < 2; i++) {
            int u = tid + i * 512;
            int r = u >> 3, sg = u & 7;
            uint32_t so = SWZ128((uint32_t)(r * 128 + sg * 16));
            size_t go = (size_t)(col0 + r) * K + kk + sg * 8;
            cpasync16(base + GT_BH + so, Bh + go);
            cpasync16(base + GT_BL + so, Bl + go);
        }
    };

    load_chunk(0, 0); CP_COMMIT();

    for (int c = 0; c < nch; c++) {
        const int buf = c & 1;
        if (c + 1 < nch) { load_chunk(c + 1, buf ^ 1); CP_COMMIT(); }
        if (c + 1 < nch) asm volatile("cp.async.wait_group 1;\n" ::: "memory");
        else             asm volatile("cp.async.wait_group 0;\n" ::: "memory");
        __syncthreads();

        const uint32_t bAH = sbase + (uint32_t)buf * GSTGB + GT_AH;
        const uint32_t bAL = bAH + (GT_AL - GT_AH);
        const uint32_t bBH = bAH + (GT_BH - GT_AH);
        const uint32_t bBL = bAH + (GT_BL - GT_AH);

        #pragma unroll
        for (int ks = 0; ks < 4; ks++) {
            const int kb = ks * 16;
            uint32_t afh[4][4], afl[4][4], bfh[2][4], bfl[2][4];
            #pragma unroll
            for (int mt = 0; mt < 4; mt++) {
                uint32_t so = SWZ128((uint32_t)((wm*64 + mt*16 + aRow) * 128 + (kb + aK) * 2));
                ldsm4(afh[mt], bAH + so);
                ldsm4(afl[mt], bAL + so);
            }
            #pragma unroll
            for (int p = 0; p < 2; p++) {
                uint32_t so = SWZ128((uint32_t)((wn*32 + p*16 + bRow) * 128 + (kb + bK) * 2));
                ldsm4(bfh[p], bBH + so);
                ldsm4(bfl[p], bBL + so);
            }
            #pragma unroll
            for (int p = 0; p < 3; p++) {
                #pragma unroll
                for (int mt = 0; mt < 4; mt++) {
                    const uint32_t* a = (p < 2) ? afh[mt] : afl[mt];
                    #pragma unroll
                    for (int nt = 0; nt < 4; nt++) {
                        const uint32_t* b = (p == 1)
                            ? &bfl[nt >> 1][(nt & 1) * 2]
                            : &bfh[nt >> 1][(nt & 1) * 2];
                        mma_bf16(acc[mt][nt], a, b);
                    }
                }
            }
        }
        __syncthreads();
    }

    #pragma unroll
    for (int mt = 0; mt < 4; mt++) {
        #pragma unroll
        for (int nt = 0; nt < 4; nt++) {
            int r  = row0 + wm * 64 + mt * 16 + g;
            int cc = col0 + wn * 32 + nt * 8 + 2 * t;
            *(float2*)&C[(size_t)r * N + cc]       = make_float2(acc[mt][nt][0], acc[mt][nt][1]);
            *(float2*)&C[(size_t)(r + 8) * N + cc] = make_float2(acc[mt][nt][2], acc[mt][nt][3]);
        }
    }
}

// ============================================================
// Banded attention, 512 threads, bf16 split mma + bias prefetch.
// NEW: band-restricted no-max softmax with __expf.
// ============================================================
#define QP   72
#define VP   200
#define PSP  196
#define OF_QH  0
#define OF_QL  9216
#define OF_KH  18432
#define OF_KL  46080
#define OF_VH  73728
#define OF_VL  99328
#define OF_PS  124928
#define OF_PH  0
#define OF_PL  25600
#define ATTN_SMEM (124928 + 64*PSP*4)

__global__ __launch_bounds__(512) void attn_kernel(const float* __restrict__ traj)
{
    extern __shared__ char asmem[];
    __nv_bfloat16* Qh = (__nv_bfloat16*)(asmem + OF_QH);
    __nv_bfloat16* Ql = (__nv_bfloat16*)(asmem + OF_QL);
    __nv_bfloat16* Kh = (__nv_bfloat16*)(asmem + OF_KH);
    __nv_bfloat16* Kl = (__nv_bfloat16*)(asmem + OF_KL);
    __nv_bfloat16* Vh = (__nv_bfloat16*)(asmem + OF_VH);
    __nv_bfloat16* Vl = (__nv_bfloat16*)(asmem + OF_VL);
    float* Ps = (float*)(asmem + OF_PS);
    __nv_bfloat16* Ph = (__nv_bfloat16*)(asmem + OF_PH);
    __nv_bfloat16* Pl = (__nv_bfloat16*)(asmem + OF_PL);

    const int tid  = threadIdx.x;
    const int lane = tid & 31, wid = tid >> 5;
    const int wm   = wid >> 2, wn = wid & 3;
    const int g    = lane >> 2, t = lane & 3;
    const int b = blockIdx.z, h = blockIdx.y;
    const int q0 = blockIdx.x * 64;
    const int k0 = q0 - 128;
    const float NEGINF = __int_as_float(0xff800000);

    const int aRow = lane & 15;
    const int aK   = (lane & 16) ? 8 : 0;
    const int bRow = (lane & 7) + ((lane & 16) ? 8 : 0);
    const int bK   = lane & 8;

    const float* qkbase = g_qkv + (size_t)b * SQ * 3072;
    const float* bias = traj + (size_t)(b * NH + h) * SQ * SQ;

    // ---- prefetch bias band into Ps ----
    {
        const uint32_t psb = smem_u32(Ps);
        #pragma unroll
        for (int i = 0; i < 6; i++) {
            int u = tid + i * 512;
            int row = u / 48;
            int c4  = u % 48;
            int kg  = k0 + c4 * 4;
            if (kg >= 0) {
                cpasync16(psb + (uint32_t)(row * PSP + c4 * 4) * 4,
                          bias + (size_t)(q0 + row) * SQ + kg);
            }
        }
        CP_COMMIT();
    }

    // ---- load Q/K/V with bf16 hi/lo split ----
    for (int idx = tid; idx < 64 * 64; idx += 512) {
        int r = idx >> 6, d = idx & 63;
        float v = qkbase[(size_t)(q0 + r) * 3072 + h * 64 + d];
        __nv_bfloat16 hh = __float2bfloat16(v);
        Qh[r * QP + d] = hh;
        Ql[r * QP + d] = __float2bfloat16(v - __bfloat162float(hh));
    }
    for (int idx = tid; idx < 192 * 64; idx += 512) {
        int kk = idx >> 6, d = idx & 63;
        int key = k0 + kk;
        float kv = 0.0f, vv = 0.0f;
        if (key >= 0) {
            const float* p = qkbase + (size_t)key * 3072 + 1024 + h * 64 + d;
            kv = p[0];
            vv = p[1024];
        }
        __nv_bfloat16 kh = __float2bfloat16(kv);
        Kh[kk * QP + d] = kh;
        Kl[kk * QP + d] = __float2bfloat16(kv - __bfloat162float(kh));
        __nv_bfloat16 vh = __float2bfloat16(vv);
        Vh[d * VP + kk] = vh;
        Vl[d * VP + kk] = __float2bfloat16(vv - __bfloat162float(vh));
    }
    __syncthreads();

    // ---- scores: 3-pass bf16 mma, warp tile 16x48 ----
    float acc[6][4];
    #pragma unroll
    for (int nt = 0; nt < 6; nt++)
        #pragma unroll
        for (int e = 0; e < 4; e++) acc[nt][e] = 0.0f;

    #pragma unroll
    for (int seg = 0; seg < 3; seg++) {
        uint32_t aq = smem_u32(seg == 2 ? Ql : Qh);
        uint32_t bk = smem_u32(seg == 1 ? Kl : Kh);
        #pragma unroll
        for (int ks = 0; ks < 4; ks++) {
            const int kb = ks * 16;
            uint32_t af[4], bfr[3][4];
            ldsm4(af, aq + 2u * ((wm * 16 + aRow) * QP + kb + aK));
            #pragma unroll
            for (int p = 0; p < 3; p++)
                ldsm4(bfr[p], bk + 2u * ((wn * 48 + p * 16 + bRow) * QP + kb + bK));
            #pragma unroll
            for (int nt = 0; nt < 6; nt++)
                mma_bf16(acc[nt], af, &bfr[nt >> 1][(nt & 1) * 2]);
        }
    }

    asm volatile("cp.async.wait_group 0;\n" ::: "memory");
    __syncthreads();

    // ---- scale + bias(smem) + mask -> Ps; zero-fill Ph/Pl (dead Q/K region) ----
    {
        #pragma unroll
        for (int nt = 0; nt < 6; nt++) {
            int rl = wm * 16 + g;
            int cl = wn * 48 + nt * 8 + 2 * t;
            #pragma unroll
            for (int e = 0; e < 4; e++) {
                int row = rl + ((e & 2) ? 8 : 0);
                int col = cl + (e & 1);
                int kg = k0 + col;
                float s;
                if (kg >= 0 && col >= row && col <= row + 128)
                    s = acc[nt][e] * 0.125f + Ps[row * PSP + col];
                else
                    s = NEGINF;
                Ps[row * PSP + col] = s;
            }
        }
        // zero cols 0..191 of Ph and Pl (pitch VP=200 halves = 100 u32)
        uint32_t* ph32 = (uint32_t*)Ph;
        uint32_t* pl32 = (uint32_t*)Pl;
        #pragma unroll
        for (int i = 0; i < 12; i++) {
            int u = tid + i * 512;            // 0..6143 = 64 rows x 96 u32
            int row = u / 96, j = u % 96;
            ph32[row * 100 + j] = 0u;
            pl32[row * 100 + j] = 0u;
        }
    }
    __syncthreads();

    // ---- band softmax: 8 thr/row over cols [row, row+128], no max shift ----
    {
        int row = tid >> 3, sub = tid & 7;
        const float* prow = Ps + row * PSP + row;   // band base
        float vals[17];
        float ssum = 0.0f;
        #pragma unroll
        for (int i = 0; i < 17; i++) {
            int cc = sub * 17 + i;
            float e = 0.0f;
            if (cc <= 128) e = __expf(prow[cc]);
            vals[i] = e;
            ssum += e;
        }
        ssum += __shfl_xor_sync(0xffffffffu, ssum, 1);
        ssum += __shfl_xor_sync(0xffffffffu, ssum, 2);
        ssum += __shfl_xor_sync(0xffffffffu, ssum, 4);
        float inv = 1.0f / ssum;
        __nv_bfloat16* phrow = Ph + row * VP + row;
        __nv_bfloat16* plrow = Pl + row * VP + row;
        #pragma unroll
        for (int i = 0; i < 17; i++) {
            int cc = sub * 17 + i;
            if (cc <= 128) {
                float pv = vals[i] * inv;
                __nv_bfloat16 hh = __float2bfloat16(pv);
                phrow[cc] = hh;
                plrow[cc] = __float2bfloat16(pv - __bfloat162float(hh));
            }
        }
    }
    __syncthreads();

    // ---- O = PV: 3-pass bf16 mma, warp tile 16x16, k=192 ----
    float o[2][4];
    #pragma unroll
    for (int nt = 0; nt < 2; nt++)
        #pragma unroll
        for (int e = 0; e < 4; e++) o[nt][e] = 0.0f;

    #pragma unroll
    for (int seg = 0; seg < 3; seg++) {
        uint32_t ap = smem_u32(seg == 2 ? Pl : Ph);
        uint32_t bv = smem_u32(seg == 1 ? Vl : Vh);
        for (int ks = 0; ks < 12; ks++) {
            const int kb = ks * 16;
            uint32_t af[4], bfr[4];
            ldsm4(af, ap + 2u * ((wm * 16 + aRow) * VP + kb + aK));
            ldsm4(bfr, bv + 2u * ((wn * 16 + bRow) * VP + kb + bK));
            #pragma unroll
            for (int nt = 0; nt < 2; nt++)
                mma_bf16(o[nt], af, &bfr[nt * 2]);
        }
    }

    // ---- epilogue: write bf16 hi/lo ----
    #pragma unroll
    for (int nt = 0; nt < 2; nt++) {
        int rl = wm * 16 + g;
        int d  = wn * 16 + nt * 8 + 2 * t;
        #pragma unroll
        for (int half_i = 0; half_i < 2; half_i++) {
            int row = rl + half_i * 8;
            float v0 = o[nt][half_i * 2 + 0];
            float v1 = o[nt][half_i * 2 + 1];
            __nv_bfloat16 h0 = __float2bfloat16(v0);
            __nv_bfloat16 h1 = __float2bfloat16(v1);
            size_t off = (size_t)(b * SQ + q0 + row) * DD + h * 64 + d;
            *(__nv_bfloat162*)(g_ah + off) = __nv_bfloat162(h0, h1);
            *(__nv_bfloat162*)(g_al + off) = __floats2bfloat162_rn(
                v0 - __bfloat162float(h0), v1 - __bfloat162float(h1));
        }
    }
}

// ============================================================
// Launch
// ============================================================
extern "C" void kernel_launch(void* const* d_in, const int* in_sizes, int n_in,
                              void* d_out, int out_size)
{
    const float* x    = (const float*)d_in[0];
    const float* traj = (const float*)d_in[1];
    const float* Wqkv = (const float*)d_in[3];
    const float* Wout = (const float*)d_in[4];
    float* out = (float*)d_out;

    void* p;
    cudaGetSymbolAddress(&p, g_qkv);  float* qkv = (float*)p;
    cudaGetSymbolAddress(&p, g_xh);   __nv_bfloat16* xh = (__nv_bfloat16*)p;
    cudaGetSymbolAddress(&p, g_xl);   __nv_bfloat16* xl = (__nv_bfloat16*)p;
    cudaGetSymbolAddress(&p, g_ah);   __nv_bfloat16* ah = (__nv_bfloat16*)p;
    cudaGetSymbolAddress(&p, g_al);   __nv_bfloat16* al = (__nv_bfloat16*)p;
    cudaGetSymbolAddress(&p, g_wqh);  __nv_bfloat16* wqh = (__nv_bfloat16*)p;
    cudaGetSymbolAddress(&p, g_wql);  __nv_bfloat16* wql = (__nv_bfloat16*)p;
    cudaGetSymbolAddress(&p, g_woh);  __nv_bfloat16* woh = (__nv_bfloat16*)p;
    cudaGetSymbolAddress(&p, g_wol);  __nv_bfloat16* wol = (__nv_bfloat16*)p;

    // split x
    {
        int n4 = MTOK * DD / 4;
        split_kernel<<<(n4 + 255) / 256, 256>>>(
            (const float4*)x, (__nv_bfloat162*)xh, (__nv_bfloat162*)xl, n4);
    }
    // transpose+split weights
    {
        dim3 grid(3072 / 32, DD / 32);
        tsplit_kernel<<<grid, dim3(32, 8)>>>(Wqkv, wqh, wql, DD, 3072);
    }
    {
        dim3 grid(DD / 32, DD / 32);
        tsplit_kernel<<<grid, dim3(32, 8)>>>(Wout, woh, wol, DD, DD);
    }
    // GEMM1: qkv = x @ W_qkv
    {
        cudaFuncSetAttribute(gemm_bf16x3,
            cudaFuncAttributeMaxDynamicSharedMemorySize, GEMM_SMEM);
        dim3 grid(3072 / 128, MTOK / 256);
        gemm_bf16x3<<<grid, 512, GEMM_SMEM>>>(xh, xl, wqh, wql, qkv, MTOK, 3072, DD);
    }
    // attention
    {
        cudaFuncSetAttribute(attn_kernel,
            cudaFuncAttributeMaxDynamicSharedMemorySize, ATTN_SMEM);
        dim3 grid(SQ / 64, NH, BB);
        attn_kernel<<<grid, 512, ATTN_SMEM>>>(traj);
    }
    // GEMM2: out = att @ W_out
    {
        dim3 grid(DD / 128, MTOK / 256);
        gemm_bf16x3<<<grid, 512, GEMM_SMEM>>>(ah, al, woh, wol, out, MTOK, DD, DD);
    }
}